// round 9
// baseline (speedup 1.0000x reference)
#include <cuda_runtime.h>
#include <math.h>

#define D 512
#define ROWS_PER_BLOCK 8
#define THREADS 256            // 8 warps, 1 row per warp, 16 elems/lane
#define RATE 0.1f
#define CLIP_MAG 8.0f
#define EPS 1e-4f
#define ACOSH_MIN 1.0001f

__global__ __launch_bounds__(THREADS, 8)
void dropout_hyperbolic_kernel(const float* __restrict__ vecs,
                               const float* __restrict__ curvature,
                               const float* __restrict__ mask_u,
                               float* __restrict__ out)
{
    const int warp = threadIdx.x >> 5;
    const int lane = threadIdx.x & 31;
    const int row  = blockIdx.x * ROWS_PER_BLOCK + warp;

    // Hoisted: curvature load + derived scalars overlap with the main loads
    // and the reduction instead of stalling the scalar tail.
    const float c = __ldg(curvature);
    const float sqrt_c = sqrtf(c);
    const float inv_keep = 1.0f / (1.0f - RATE);

    const float4* vp = reinterpret_cast<const float4*>(vecs  + row * D);
    const float4* mp = reinterpret_cast<const float4*>(mask_u + row * D);
    float4*       op = reinterpret_cast<float4*>(out + row * D);

    // Front-batched, fully-coalesced loads: chunk i covers elements
    // [i*128 + lane*4, +4). 8 LDG.128 in flight per thread.
    float4 v[4], m[4];
    #pragma unroll
    for (int i = 0; i < 4; i++) v[i] = vp[lane + i * 32];
    #pragma unroll
    for (int i = 0; i < 4; i++) m[i] = mp[lane + i * 32];

    // Row element 0 (lane 0, chunk 0, .x) is the hyperboloid coordinate:
    // excluded from both sums; its output is overwritten below anyway.
    if (lane == 0) v[0].x = 0.0f;

    // Pack keep decisions into a 16-bit mask (bit 4*i+j for chunk i comp j)
    // and accumulate s = sum v^2, sk = sum v^2*keep in the same pass.
    unsigned bits = 0u;
    float s_loc = 0.0f, sk_loc = 0.0f;
    #pragma unroll
    for (int i = 0; i < 4; i++) {
        bool b0 = (m[i].x >= RATE);
        bool b1 = (m[i].y >= RATE);
        bool b2 = (m[i].z >= RATE);
        bool b3 = (m[i].w >= RATE);
        bits |= (unsigned(b0) << (4*i)) | (unsigned(b1) << (4*i+1))
              | (unsigned(b2) << (4*i+2)) | (unsigned(b3) << (4*i+3));
        float x0 = v[i].x * v[i].x;
        float x1 = v[i].y * v[i].y;
        float x2 = v[i].z * v[i].z;
        float x3 = v[i].w * v[i].w;
        s_loc += x0 + x1 + x2 + x3;
        sk_loc += (b0 ? x0 : 0.0f) + (b1 ? x1 : 0.0f)
                + (b2 ? x2 : 0.0f) + (b3 ? x3 : 0.0f);
    }

    // Butterfly reduce — all lanes end with the row totals. No barriers.
    #pragma unroll
    for (int off = 16; off > 0; off >>= 1) {
        s_loc  += __shfl_xor_sync(0xFFFFFFFFu, s_loc,  off);
        sk_loc += __shfl_xor_sync(0xFFFFFFFFu, sk_loc, off);
    }

    // Per-row scalar tail, computed redundantly by all 32 lanes (warp-wide
    // issue: same cost as 1 lane, no broadcast needed).
    float arg = sqrtf(c + s_loc) / sqrt_c - EPS;
    arg = fmaxf(arg, ACOSH_MIN);
    // acosh(x) = log(x + sqrt(x^2 - 1)); arg >= 1.0001 so stable.
    float dist = sqrt_c * __logf(arg + sqrtf(fmaf(arg, arg, -1.0f)));
    float scale1 = dist / (sqrtf(s_loc) + EPS);

    float t = scale1 * scale1 * sk_loc * (inv_keep * inv_keep);
    float snv = sqrtf(t) / sqrt_c + EPS;
    float snv_c = fminf(fmaxf(snv, -CLIP_MAG), CLIP_MAG);

    float e  = __expf(snv_c);
    float ei = 1.0f / e;
    float cosh_v = 0.5f * (e + ei);
    float sinh_v = 0.5f * (e - ei);

    const float oscale    = (sinh_v / snv) * scale1 * inv_keep;
    const float first_val = cosh_v * sqrt_c;

    // Output pass: reconstruct dropped values from the bitmask.
    // Streaming stores (evict-first): the output is never read, so keep it
    // from evicting the L2-resident inputs between graph replays.
    #pragma unroll
    for (int i = 0; i < 4; i++) {
        float4 r;
        r.x = (bits & (1u << (4*i)))   ? oscale * v[i].x : 0.0f;
        r.y = (bits & (1u << (4*i+1))) ? oscale * v[i].y : 0.0f;
        r.z = (bits & (1u << (4*i+2))) ? oscale * v[i].z : 0.0f;
        r.w = (bits & (1u << (4*i+3))) ? oscale * v[i].w : 0.0f;
        if (i == 0 && lane == 0) r.x = first_val;  // out[row][0]
        __stcs(op + lane + i * 32, r);
    }
}

extern "C" void kernel_launch(void* const* d_in, const int* in_sizes, int n_in,
                              void* d_out, int out_size)
{
    const float* vecs      = (const float*)d_in[0];
    const float* curvature = (const float*)d_in[1];
    const float* mask_u    = (const float*)d_in[2];
    float* out = (float*)d_out;

    const int n_rows = in_sizes[0] / D;                 // 16384
    const int blocks = n_rows / ROWS_PER_BLOCK;         // 2048
    dropout_hyperbolic_kernel<<<blocks, THREADS>>>(vecs, curvature, mask_u, out);
}

// round 10
// speedup vs baseline: 1.2548x; 1.2548x over previous
#include <cuda_runtime.h>
#include <math.h>

#define D 512
#define ROWS_PER_BLOCK 8
#define THREADS 256            // 8 warps, 1 row per warp, 16 elems/lane
#define RATE 0.1f
#define CLIP_MAG 8.0f
#define EPS 1e-4f
#define ACOSH_MIN 1.0001f

__global__ __launch_bounds__(THREADS, 8)
void dropout_hyperbolic_kernel(const float* __restrict__ vecs,
                               const float* __restrict__ curvature,
                               const float* __restrict__ mask_u,
                               float* __restrict__ out)
{
    const int warp = threadIdx.x >> 5;
    const int lane = threadIdx.x & 31;
    const int row  = blockIdx.x * ROWS_PER_BLOCK + warp;

    const float4* vp = reinterpret_cast<const float4*>(vecs  + row * D);
    const float4* mp = reinterpret_cast<const float4*>(mask_u + row * D);
    float4*       op = reinterpret_cast<float4*>(out + row * D);

    // Front-batched, fully-coalesced loads: chunk i covers elements
    // [i*128 + lane*4, +4). 8 LDG.128 in flight per thread.
    // NOTE: the scalar curvature load must stay AFTER these (R9 showed that
    // issuing a same-line scalar load first pollutes the L1tex queue).
    float4 v[4], m[4];
    #pragma unroll
    for (int i = 0; i < 4; i++) v[i] = vp[lane + i * 32];
    #pragma unroll
    for (int i = 0; i < 4; i++) m[i] = mp[lane + i * 32];

    // Row element 0 (lane 0, chunk 0, .x) is the hyperboloid coordinate:
    // excluded from both sums; its output is overwritten below anyway.
    if (lane == 0) v[0].x = 0.0f;

    // Pack keep decisions into a 16-bit mask (bit 4*i+j for chunk i comp j)
    // and accumulate s = sum v^2, sk = sum v^2*keep in the same pass.
    unsigned bits = 0u;
    float s_loc = 0.0f, sk_loc = 0.0f;
    #pragma unroll
    for (int i = 0; i < 4; i++) {
        bool b0 = (m[i].x >= RATE);
        bool b1 = (m[i].y >= RATE);
        bool b2 = (m[i].z >= RATE);
        bool b3 = (m[i].w >= RATE);
        bits |= (unsigned(b0) << (4*i)) | (unsigned(b1) << (4*i+1))
              | (unsigned(b2) << (4*i+2)) | (unsigned(b3) << (4*i+3));
        float x0 = v[i].x * v[i].x;
        float x1 = v[i].y * v[i].y;
        float x2 = v[i].z * v[i].z;
        float x3 = v[i].w * v[i].w;
        s_loc += x0 + x1 + x2 + x3;
        sk_loc += (b0 ? x0 : 0.0f) + (b1 ? x1 : 0.0f)
                + (b2 ? x2 : 0.0f) + (b3 ? x3 : 0.0f);
    }

    // Butterfly reduce — all lanes end with the row totals. No barriers.
    #pragma unroll
    for (int off = 16; off > 0; off >>= 1) {
        s_loc  += __shfl_xor_sync(0xFFFFFFFFu, s_loc,  off);
        sk_loc += __shfl_xor_sync(0xFFFFFFFFu, sk_loc, off);
    }

    // Per-row scalar tail, computed redundantly by all 32 lanes (warp-wide
    // issue: same cost as 1 lane, no broadcast needed).
    const float c = __ldg(curvature);
    const float sqrt_c = sqrtf(c);
    const float inv_keep = 1.0f / (1.0f - RATE);

    float arg = sqrtf(c + s_loc) / sqrt_c - EPS;
    arg = fmaxf(arg, ACOSH_MIN);
    // acosh(x) = log(x + sqrt(x^2 - 1)); arg >= 1.0001 so stable.
    float dist = sqrt_c * __logf(arg + sqrtf(fmaf(arg, arg, -1.0f)));
    float scale1 = dist / (sqrtf(s_loc) + EPS);

    float t = scale1 * scale1 * sk_loc * (inv_keep * inv_keep);
    float snv = sqrtf(t) / sqrt_c + EPS;
    float snv_c = fminf(fmaxf(snv, -CLIP_MAG), CLIP_MAG);

    float e  = __expf(snv_c);
    float ei = 1.0f / e;
    float cosh_v = 0.5f * (e + ei);
    float sinh_v = 0.5f * (e - ei);

    const float oscale    = (sinh_v / snv) * scale1 * inv_keep;
    const float first_val = cosh_v * sqrt_c;

    // Output pass: reconstruct dropped values from the bitmask.
    // Streaming stores (evict-first): the output is never read, so keep it
    // from evicting the L2-resident inputs between graph replays.
    #pragma unroll
    for (int i = 0; i < 4; i++) {
        float4 r;
        r.x = (bits & (1u << (4*i)))   ? oscale * v[i].x : 0.0f;
        r.y = (bits & (1u << (4*i+1))) ? oscale * v[i].y : 0.0f;
        r.z = (bits & (1u << (4*i+2))) ? oscale * v[i].z : 0.0f;
        r.w = (bits & (1u << (4*i+3))) ? oscale * v[i].w : 0.0f;
        if (i == 0 && lane == 0) r.x = first_val;  // out[row][0]
        __stcs(op + lane + i * 32, r);
    }
}

extern "C" void kernel_launch(void* const* d_in, const int* in_sizes, int n_in,
                              void* d_out, int out_size)
{
    const float* vecs      = (const float*)d_in[0];
    const float* curvature = (const float*)d_in[1];
    const float* mask_u    = (const float*)d_in[2];
    float* out = (float*)d_out;

    const int n_rows = in_sizes[0] / D;                 // 16384
    const int blocks = n_rows / ROWS_PER_BLOCK;         // 2048
    dropout_hyperbolic_kernel<<<blocks, THREADS>>>(vecs, curvature, mask_u, out);
}

// round 12
// speedup vs baseline: 1.3104x; 1.0443x over previous
#include <cuda_runtime.h>
#include <math.h>

#define D 512
#define ROWS_PER_BLOCK 8
#define THREADS 256            // 8 warps, 1 row per warp, 16 elems/lane
#define RATE 0.1f
#define CLIP_MAG 8.0f
#define EPS 1e-4f
#define ACOSH_MIN 1.0001f

__global__ __launch_bounds__(THREADS, 8)
void dropout_hyperbolic_kernel(const float* __restrict__ vecs,
                               const float* __restrict__ curvature,
                               const float* __restrict__ mask_u,
                               float* __restrict__ out)
{
    const int warp = threadIdx.x >> 5;
    const int lane = threadIdx.x & 31;
    const int row  = blockIdx.x * ROWS_PER_BLOCK + warp;

    const float4* vp = reinterpret_cast<const float4*>(vecs  + row * D);
    const float4* mp = reinterpret_cast<const float4*>(mask_u + row * D);
    float4*       op = reinterpret_cast<float4*>(out + row * D);

    // Front-batched, fully-coalesced loads: chunk i covers elements
    // [i*128 + lane*4, +4). 8 LDG.128 in flight per thread.
    // NOTE (validated R9): the scalar curvature load must stay AFTER these —
    // issuing a same-line scalar load first pollutes the L1tex queue.
    float4 v[4], m[4];
    #pragma unroll
    for (int i = 0; i < 4; i++) v[i] = vp[lane + i * 32];
    #pragma unroll
    for (int i = 0; i < 4; i++) m[i] = mp[lane + i * 32];

    // Row element 0 (lane 0, chunk 0, .x) is the hyperboloid coordinate:
    // excluded from both sums; its output is overwritten below anyway.
    if (lane == 0) v[0].x = 0.0f;

    // Pack keep decisions into a 16-bit mask (bit 4*i+j for chunk i comp j)
    // and accumulate s = sum v^2, sk = sum v^2*keep in the same pass.
    unsigned bits = 0u;
    float s_loc = 0.0f, sk_loc = 0.0f;
    #pragma unroll
    for (int i = 0; i < 4; i++) {
        bool b0 = (m[i].x >= RATE);
        bool b1 = (m[i].y >= RATE);
        bool b2 = (m[i].z >= RATE);
        bool b3 = (m[i].w >= RATE);
        bits |= (unsigned(b0) << (4*i)) | (unsigned(b1) << (4*i+1))
              | (unsigned(b2) << (4*i+2)) | (unsigned(b3) << (4*i+3));
        float x0 = v[i].x * v[i].x;
        float x1 = v[i].y * v[i].y;
        float x2 = v[i].z * v[i].z;
        float x3 = v[i].w * v[i].w;
        s_loc += x0 + x1 + x2 + x3;
        sk_loc += (b0 ? x0 : 0.0f) + (b1 ? x1 : 0.0f)
                + (b2 ? x2 : 0.0f) + (b3 ? x3 : 0.0f);
    }

    // Butterfly reduce — all lanes end with the row totals. No barriers.
    // (redux.sync.add.f32 does not exist on sm_103 — R11.)
    #pragma unroll
    for (int off = 16; off > 0; off >>= 1) {
        s_loc  += __shfl_xor_sync(0xFFFFFFFFu, s_loc,  off);
        sk_loc += __shfl_xor_sync(0xFFFFFFFFu, sk_loc, off);
    }

    // Per-row scalar tail, computed redundantly by all 32 lanes (warp-wide
    // issue: same cost as 1 lane, no broadcast needed).
    const float c = __ldg(curvature);
    const float sqrt_c = sqrtf(c);
    const float inv_keep = 1.0f / (1.0f - RATE);

    float arg = sqrtf(c + s_loc) / sqrt_c - EPS;
    arg = fmaxf(arg, ACOSH_MIN);
    // acosh(x) = log(x + sqrt(x^2 - 1)); arg >= 1.0001 so stable.
    float dist = sqrt_c * __logf(arg + sqrtf(fmaf(arg, arg, -1.0f)));
    float scale1 = dist / (sqrtf(s_loc) + EPS);

    float t = scale1 * scale1 * sk_loc * (inv_keep * inv_keep);
    float snv = sqrtf(t) / sqrt_c + EPS;
    float snv_c = fminf(fmaxf(snv, -CLIP_MAG), CLIP_MAG);

    float e  = __expf(snv_c);
    float ei = 1.0f / e;
    float cosh_v = 0.5f * (e + ei);
    float sinh_v = 0.5f * (e - ei);

    const float oscale    = (sinh_v / snv) * scale1 * inv_keep;
    const float first_val = cosh_v * sqrt_c;

    // Output pass: reconstruct dropped values from the bitmask.
    // Streaming stores (evict-first): the output is never read, so keep it
    // from evicting the L2-resident inputs between graph replays.
    #pragma unroll
    for (int i = 0; i < 4; i++) {
        float4 r;
        r.x = (bits & (1u << (4*i)))   ? oscale * v[i].x : 0.0f;
        r.y = (bits & (1u << (4*i+1))) ? oscale * v[i].y : 0.0f;
        r.z = (bits & (1u << (4*i+2))) ? oscale * v[i].z : 0.0f;
        r.w = (bits & (1u << (4*i+3))) ? oscale * v[i].w : 0.0f;
        if (i == 0 && lane == 0) r.x = first_val;  // out[row][0]
        __stcs(op + lane + i * 32, r);
    }
}

extern "C" void kernel_launch(void* const* d_in, const int* in_sizes, int n_in,
                              void* d_out, int out_size)
{
    const float* vecs      = (const float*)d_in[0];
    const float* curvature = (const float*)d_in[1];
    const float* mask_u    = (const float*)d_in[2];
    float* out = (float*)d_out;

    const int n_rows = in_sizes[0] / D;                 // 16384
    const int blocks = n_rows / ROWS_PER_BLOCK;         // 2048
    dropout_hyperbolic_kernel<<<blocks, THREADS>>>(vecs, curvature, mask_u, out);
}